// round 1
// baseline (speedup 1.0000x reference)
#include <cuda_runtime.h>

#define Bb   4
#define Ss   4096
#define FIN  512
#define FOUT 512
#define KW   17
#define Gg   8
#define Dd   64
#define PADK 8
#define Mrows (Bb*Ss)   // 16384

// Scratch (static device globals — allocation-free per harness rules)
__device__ float g_q[(size_t)Mrows*FOUT];
__device__ float g_k[(size_t)Mrows*FOUT];
__device__ float g_v[(size_t)Mrows*FOUT];

// ---------------------------------------------------------------------------
// GEMM: C[m,n] = sum_f A[m,f] * W[n,f]   (A row-major [M,FIN], W row-major [FOUT,FIN])
// 128x128 tile, BK=8, 256 threads, 8x8 per thread. blockIdx.z selects q/k/v.
// ---------------------------------------------------------------------------
__global__ __launch_bounds__(256) void gemm_qkv(
    const float* __restrict__ x,
    const float* __restrict__ Wq,
    const float* __restrict__ Wk,
    const float* __restrict__ Wv)
{
    const float* __restrict__ W = (blockIdx.z == 0) ? Wq : (blockIdx.z == 1) ? Wk : Wv;
    float* __restrict__ C       = (blockIdx.z == 0) ? g_q : (blockIdx.z == 1) ? g_k : g_v;

    __shared__ float As[8][128];
    __shared__ float Bs[8][128];

    const int tid = threadIdx.x;
    const int m0 = blockIdx.y * 128;
    const int n0 = blockIdx.x * 128;

    // global-load mapping: each thread loads one float4 of A and one of B
    const int lr = tid >> 1;          // 0..127 tile row
    const int lc = (tid & 1) * 4;     // 0 or 4 within BK=8

    // compute mapping: 16x16 thread grid, 8x8 micro-tile
    const int ty = tid >> 4;          // 0..15 -> rows ty*8..ty*8+7
    const int tx = tid & 15;          // 0..15 -> cols tx*8..tx*8+7

    float acc[8][8];
#pragma unroll
    for (int i = 0; i < 8; i++)
#pragma unroll
        for (int j = 0; j < 8; j++) acc[i][j] = 0.f;

    const float* aptr = x + (size_t)(m0 + lr) * FIN + lc;
    const float* bptr = W + (size_t)(n0 + lr) * FIN + lc;

    for (int k0 = 0; k0 < FIN; k0 += 8) {
        float4 av = *(const float4*)(aptr + k0);
        float4 bv = *(const float4*)(bptr + k0);
        __syncthreads();   // protect previous iteration's compute
        As[lc + 0][lr] = av.x; As[lc + 1][lr] = av.y;
        As[lc + 2][lr] = av.z; As[lc + 3][lr] = av.w;
        Bs[lc + 0][lr] = bv.x; Bs[lc + 1][lr] = bv.y;
        Bs[lc + 2][lr] = bv.z; Bs[lc + 3][lr] = bv.w;
        __syncthreads();
#pragma unroll
        for (int kk = 0; kk < 8; kk++) {
            float a[8], b[8];
            *(float4*)&a[0] = *(const float4*)&As[kk][ty * 8];
            *(float4*)&a[4] = *(const float4*)&As[kk][ty * 8 + 4];
            *(float4*)&b[0] = *(const float4*)&Bs[kk][tx * 8];
            *(float4*)&b[4] = *(const float4*)&Bs[kk][tx * 8 + 4];
#pragma unroll
            for (int i = 0; i < 8; i++)
#pragma unroll
                for (int j = 0; j < 8; j++)
                    acc[i][j] = fmaf(a[i], b[j], acc[i][j]);
        }
    }

#pragma unroll
    for (int i = 0; i < 8; i++) {
        float* crow = C + (size_t)(m0 + ty * 8 + i) * FOUT + n0 + tx * 8;
        *(float4*)&crow[0] = make_float4(acc[i][0], acc[i][1], acc[i][2], acc[i][3]);
        *(float4*)&crow[4] = make_float4(acc[i][4], acc[i][5], acc[i][6], acc[i][7]);
    }
}

// ---------------------------------------------------------------------------
// Attention: one warp per (b, s, g). Lane handles 2 feature dims (D=64).
// energy_j = sum_d q_d * (k[s+j-PAD]_d + rel[d,j]); softmax over j; out = attn·v.
// Out-of-range window rows: k = 0 (rel term remains), v = 0.
// Block = 8 warps covering 8 consecutive s for fixed (b, g).
// ---------------------------------------------------------------------------
__global__ __launch_bounds__(256) void attn_kernel(
    const float* __restrict__ rel,     // [FOUT, KW]
    float* __restrict__ out,           // [Mrows, FOUT]
    float* __restrict__ attn_out)      // [Mrows, Gg, KW]
{
    const int b    = blockIdx.z;
    const int g    = blockIdx.y;
    const int warp = threadIdx.x >> 5;
    const int lane = threadIdx.x & 31;
    const int s    = blockIdx.x * 8 + warp;
    const int m    = b * Ss + s;
    const int o    = g * Dd + 2 * lane;

    const float2 q2 = *(const float2*)&g_q[(size_t)m * FOUT + o];
    const float* relp = rel + (size_t)o * KW;   // rel[o][j], next dim at +KW

    float e[KW];
#pragma unroll
    for (int j = 0; j < KW; j++) {
        const int r = s + j - PADK;
        float kx = 0.f, ky = 0.f;
        if (r >= 0 && r < Ss) {
            float2 k2 = *(const float2*)&g_k[(size_t)(b * Ss + r) * FOUT + o];
            kx = k2.x; ky = k2.y;
        }
        kx += relp[j];
        ky += relp[KW + j];
        float ej = q2.x * kx + q2.y * ky;
#pragma unroll
        for (int off = 16; off > 0; off >>= 1)
            ej += __shfl_xor_sync(0xffffffffu, ej, off);
        e[j] = ej;   // all lanes hold full sum
    }

    // softmax over KW (redundant across lanes — no comm needed)
    float mx = e[0];
#pragma unroll
    for (int j = 1; j < KW; j++) mx = fmaxf(mx, e[j]);
    float sum = 0.f;
#pragma unroll
    for (int j = 0; j < KW; j++) { e[j] = __expf(e[j] - mx); sum += e[j]; }
    const float inv = 1.f / sum;
#pragma unroll
    for (int j = 0; j < KW; j++) e[j] *= inv;

    if (lane < KW)
        attn_out[((size_t)m * Gg + g) * KW + lane] = e[lane];

    float ax = 0.f, ay = 0.f;
#pragma unroll
    for (int j = 0; j < KW; j++) {
        const int r = s + j - PADK;
        if (r >= 0 && r < Ss) {
            float2 v2 = *(const float2*)&g_v[(size_t)(b * Ss + r) * FOUT + o];
            ax = fmaf(e[j], v2.x, ax);
            ay = fmaf(e[j], v2.y, ay);
        }
    }
    *(float2*)&out[(size_t)m * FOUT + o] = make_float2(ax, ay);
}

// ---------------------------------------------------------------------------
extern "C" void kernel_launch(void* const* d_in, const int* in_sizes, int n_in,
                              void* d_out, int out_size)
{
    const float* x   = (const float*)d_in[0];
    const float* Wq  = (const float*)d_in[1];
    const float* Wk  = (const float*)d_in[2];
    const float* Wv  = (const float*)d_in[3];
    const float* rel = (const float*)d_in[4];

    float* out  = (float*)d_out;
    float* attn = out + (size_t)Mrows * FOUT;

    dim3 gg(FOUT / 128, Mrows / 128, 3);
    gemm_qkv<<<gg, 256>>>(x, Wq, Wk, Wv);

    dim3 ga(Ss / 8, Gg, Bb);
    attn_kernel<<<ga, 256>>>(rel, out, attn);
}

// round 3
// speedup vs baseline: 1.3283x; 1.3283x over previous
#include <cuda_runtime.h>
#include <cstdint>

#define Bb   4
#define Ss   4096
#define FIN  512
#define FOUT 512
#define KW   17
#define Gg   8
#define Dd   64
#define PADK 8
#define Mrows (Bb*Ss)   // 16384

// Scratch (static device globals — allocation-free per harness rules)
__device__ float g_q[(size_t)Mrows*FOUT];
__device__ float g_k[(size_t)Mrows*FOUT];
__device__ float g_v[(size_t)Mrows*FOUT];

// ---------------------------------------------------------------------------
// tf32 helpers
// ---------------------------------------------------------------------------
__device__ __forceinline__ void split_tf32(float a, uint32_t& hi, uint32_t& lo) {
    uint32_t h;
    asm("cvt.rna.tf32.f32 %0, %1;" : "=r"(h) : "f"(a));
    float r = a - __uint_as_float(h);
    uint32_t l;
    asm("cvt.rna.tf32.f32 %0, %1;" : "=r"(l) : "f"(r));
    hi = h; lo = l;
}

__device__ __forceinline__ void mma_tf32(float* d, const uint32_t* a, const uint32_t* b) {
    asm volatile(
        "mma.sync.aligned.m16n8k8.row.col.f32.tf32.tf32.f32 "
        "{%0,%1,%2,%3}, {%4,%5,%6,%7}, {%8,%9}, {%0,%1,%2,%3};"
        : "+f"(d[0]), "+f"(d[1]), "+f"(d[2]), "+f"(d[3])
        : "r"(a[0]), "r"(a[1]), "r"(a[2]), "r"(a[3]), "r"(b[0]), "r"(b[1]));
}

__device__ __forceinline__ void cp_async16(void* smem, const void* gmem) {
    uint32_t s = (uint32_t)__cvta_generic_to_shared(smem);
    asm volatile("cp.async.cg.shared.global [%0], [%1], 16;" :: "r"(s), "l"(gmem));
}
__device__ __forceinline__ void cp_commit() { asm volatile("cp.async.commit_group;"); }
__device__ __forceinline__ void cp_wait0() { asm volatile("cp.async.wait_group 0;"); }

// ---------------------------------------------------------------------------
// GEMM via mma.sync tf32 (3xTF32 split for fp32-grade accuracy)
// C[m,n] = sum_f A[m,f] * W[n,f]; A [M,512] row-major, W [512,512] row-major.
// Block tile 128x128, BK=16, 256 threads (8 warps, warp tile 32x64).
// Smem raw fp32 tiles [row][k] with stride 20 (conflict-free for quad pattern),
// double-buffered via cp.async. hi/lo split done at fragment-load time.
// blockIdx.z selects q/k/v.
// ---------------------------------------------------------------------------
#define SSTR 20   // smem row stride in floats (16 + 4 pad)

__global__ __launch_bounds__(256) void gemm_qkv(
    const float* __restrict__ x,
    const float* __restrict__ Wq,
    const float* __restrict__ Wk,
    const float* __restrict__ Wv)
{
    const float* __restrict__ W = (blockIdx.z == 0) ? Wq : (blockIdx.z == 1) ? Wk : Wv;
    float* __restrict__ C       = (blockIdx.z == 0) ? g_q : (blockIdx.z == 1) ? g_k : g_v;

    __shared__ float As[2][128 * SSTR];
    __shared__ float Bs[2][128 * SSTR];

    const int tid  = threadIdx.x;
    const int m0   = blockIdx.y * 128;
    const int n0   = blockIdx.x * 128;

    // global->smem mapping: each thread owns 8 consecutive k of one row (2x cp.async16)
    const int lrow = tid >> 1;            // 0..127
    const int lk   = (tid & 1) * 8;       // 0 or 8

    const float* agp = x + (size_t)(m0 + lrow) * FIN + lk;
    const float* bgp = W + (size_t)(n0 + lrow) * FIN + lk;
    float* asp = &As[0][lrow * SSTR + lk];  // buffer 0 base; buffer 1 at +128*SSTR
    float* bsp = &Bs[0][lrow * SSTR + lk];

    // warp tiling
    const int warp  = tid >> 5;
    const int lane  = tid & 31;
    const int wm0   = (warp >> 1) * 32;   // 4 warps along M
    const int wn0   = (warp & 1) * 64;    // 2 warps along N
    const int gid   = lane >> 2;          // 0..7
    const int tig   = lane & 3;           // 0..3

    float acc[2][8][4];
#pragma unroll
    for (int mt = 0; mt < 2; mt++)
#pragma unroll
        for (int nt = 0; nt < 8; nt++)
#pragma unroll
            for (int i = 0; i < 4; i++) acc[mt][nt][i] = 0.f;

    const int NT = FIN / 16;   // 32 k-tiles

    // prologue: issue tile 0 into buffer 0
    cp_async16(asp,     agp);
    cp_async16(asp + 4, agp + 4);
    cp_async16(bsp,     bgp);
    cp_async16(bsp + 4, bgp + 4);
    cp_commit();

    for (int t = 0; t < NT; t++) {
        cp_wait0();
        __syncthreads();

        // issue next tile into other buffer
        if (t + 1 < NT) {
            const int nb = (t + 1) & 1;
            const int ko = (t + 1) * 16;
            cp_async16(asp + nb * 128 * SSTR,     agp + ko);
            cp_async16(asp + nb * 128 * SSTR + 4, agp + ko + 4);
            cp_async16(bsp + nb * 128 * SSTR,     bgp + ko);
            cp_async16(bsp + nb * 128 * SSTR + 4, bgp + ko + 4);
            cp_commit();
        }

        const float* Ab = As[t & 1];
        const float* Bbuf = Bs[t & 1];

#pragma unroll
        for (int kt = 0; kt < 16; kt += 8) {
            // A fragments (2 m-tiles): hi/lo split
            uint32_t ahi[2][4], alo[2][4];
#pragma unroll
            for (int mt = 0; mt < 2; mt++) {
                const int r0 = wm0 + mt * 16 + gid;
                float a0 = Ab[(r0    ) * SSTR + kt + tig];
                float a1 = Ab[(r0 + 8) * SSTR + kt + tig];
                float a2 = Ab[(r0    ) * SSTR + kt + tig + 4];
                float a3 = Ab[(r0 + 8) * SSTR + kt + tig + 4];
                split_tf32(a0, ahi[mt][0], alo[mt][0]);
                split_tf32(a1, ahi[mt][1], alo[mt][1]);
                split_tf32(a2, ahi[mt][2], alo[mt][2]);
                split_tf32(a3, ahi[mt][3], alo[mt][3]);
            }
#pragma unroll
            for (int nt = 0; nt < 8; nt++) {
                const int n = wn0 + nt * 8 + gid;
                float b0 = Bbuf[n * SSTR + kt + tig];
                float b1 = Bbuf[n * SSTR + kt + tig + 4];
                uint32_t bhi[2], blo[2];
                split_tf32(b0, bhi[0], blo[0]);
                split_tf32(b1, bhi[1], blo[1]);
#pragma unroll
                for (int mt = 0; mt < 2; mt++) {
                    mma_tf32(acc[mt][nt], ahi[mt], bhi);   // hi*hi
                    mma_tf32(acc[mt][nt], ahi[mt], blo);   // hi*lo
                    mma_tf32(acc[mt][nt], alo[mt], bhi);   // lo*hi
                }
            }
        }
        __syncthreads();
    }

    // epilogue: accum layout c0:(r=gid, c=2*tig) c1:(r, c+1) c2:(r+8, c) c3:(r+8, c+1)
#pragma unroll
    for (int mt = 0; mt < 2; mt++) {
#pragma unroll
        for (int nt = 0; nt < 8; nt++) {
            const int row = m0 + wm0 + mt * 16 + gid;
            const int col = n0 + wn0 + nt * 8 + 2 * tig;
            *(float2*)&C[(size_t)row * FOUT + col] =
                make_float2(acc[mt][nt][0], acc[mt][nt][1]);
            *(float2*)&C[(size_t)(row + 8) * FOUT + col] =
                make_float2(acc[mt][nt][2], acc[mt][nt][3]);
        }
    }
}

// ---------------------------------------------------------------------------
// Attention: one warp per (b, s, g). Lane handles 2 feature dims (D=64).
// ---------------------------------------------------------------------------
__global__ __launch_bounds__(256) void attn_kernel(
    const float* __restrict__ rel,     // [FOUT, KW]
    float* __restrict__ out,           // [Mrows, FOUT]
    float* __restrict__ attn_out)      // [Mrows, Gg, KW]
{
    const int b    = blockIdx.z;
    const int g    = blockIdx.y;
    const int warp = threadIdx.x >> 5;
    const int lane = threadIdx.x & 31;
    const int s    = blockIdx.x * 8 + warp;
    const int m    = b * Ss + s;
    const int o    = g * Dd + 2 * lane;

    const float2 q2 = *(const float2*)&g_q[(size_t)m * FOUT + o];
    const float* relp = rel + (size_t)o * KW;

    float e[KW];
#pragma unroll
    for (int j = 0; j < KW; j++) {
        const int r = s + j - PADK;
        float kx = 0.f, ky = 0.f;
        if (r >= 0 && r < Ss) {
            float2 k2 = *(const float2*)&g_k[(size_t)(b * Ss + r) * FOUT + o];
            kx = k2.x; ky = k2.y;
        }
        kx += relp[j];
        ky += relp[KW + j];
        float ej = q2.x * kx + q2.y * ky;
#pragma unroll
        for (int off = 16; off > 0; off >>= 1)
            ej += __shfl_xor_sync(0xffffffffu, ej, off);
        e[j] = ej;
    }

    float mx = e[0];
#pragma unroll
    for (int j = 1; j < KW; j++) mx = fmaxf(mx, e[j]);
    float sum = 0.f;
#pragma unroll
    for (int j = 0; j < KW; j++) { e[j] = __expf(e[j] - mx); sum += e[j]; }
    const float inv = 1.f / sum;
#pragma unroll
    for (int j = 0; j < KW; j++) e[j] *= inv;

    if (lane < KW)
        attn_out[((size_t)m * Gg + g) * KW + lane] = e[lane];

    float ax = 0.f, ay = 0.f;
#pragma unroll
    for (int j = 0; j < KW; j++) {
        const int r = s + j - PADK;
        if (r >= 0 && r < Ss) {
            float2 v2 = *(const float2*)&g_v[(size_t)(b * Ss + r) * FOUT + o];
            ax = fmaf(e[j], v2.x, ax);
            ay = fmaf(e[j], v2.y, ay);
        }
    }
    *(float2*)&out[(size_t)m * FOUT + o] = make_float2(ax, ay);
}

// ---------------------------------------------------------------------------
extern "C" void kernel_launch(void* const* d_in, const int* in_sizes, int n_in,
                              void* d_out, int out_size)
{
    const float* x   = (const float*)d_in[0];
    const float* Wq  = (const float*)d_in[1];
    const float* Wk  = (const float*)d_in[2];
    const float* Wv  = (const float*)d_in[3];
    const float* rel = (const float*)d_in[4];

    float* out  = (float*)d_out;
    float* attn = out + (size_t)Mrows * FOUT;

    dim3 gg(FOUT / 128, Mrows / 128, 3);
    gemm_qkv<<<gg, 256>>>(x, Wq, Wk, Wv);

    dim3 ga(Ss / 8, Gg, Bb);
    attn_kernel<<<ga, 256>>>(rel, out, attn);
}

// round 5
// speedup vs baseline: 1.3870x; 1.0442x over previous
#include <cuda_runtime.h>
#include <cstdint>

#define Bb   4
#define Ss   4096
#define FIN  512
#define FOUT 512
#define KW   17
#define Gg   8
#define Dd   64
#define PADK 8
#define Mrows (Bb*Ss)   // 16384

__device__ float g_q[(size_t)Mrows*FOUT];
__device__ float g_k[(size_t)Mrows*FOUT];
__device__ float g_v[(size_t)Mrows*FOUT];

// ---------------------------------------------------------------------------
__device__ __forceinline__ void split_tf32(float a, uint32_t& hi, uint32_t& lo) {
    uint32_t h;
    asm("cvt.rna.tf32.f32 %0, %1;" : "=r"(h) : "f"(a));
    float r = a - __uint_as_float(h);
    uint32_t l;
    asm("cvt.rna.tf32.f32 %0, %1;" : "=r"(l) : "f"(r));
    hi = h; lo = l;
}

__device__ __forceinline__ void mma_tf32(float* d, const uint32_t* a, const uint32_t* b) {
    asm volatile(
        "mma.sync.aligned.m16n8k8.row.col.f32.tf32.tf32.f32 "
        "{%0,%1,%2,%3}, {%4,%5,%6,%7}, {%8,%9}, {%0,%1,%2,%3};"
        : "+f"(d[0]), "+f"(d[1]), "+f"(d[2]), "+f"(d[3])
        : "r"(a[0]), "r"(a[1]), "r"(a[2]), "r"(a[3]), "r"(b[0]), "r"(b[1]));
}

__device__ __forceinline__ void cp_async16(void* smem, const void* gmem) {
    uint32_t s = (uint32_t)__cvta_generic_to_shared(smem);
    asm volatile("cp.async.cg.shared.global [%0], [%1], 16;" :: "r"(s), "l"(gmem));
}
__device__ __forceinline__ void cp_commit() { asm volatile("cp.async.commit_group;"); }
__device__ __forceinline__ void cp_wait0() { asm volatile("cp.async.wait_group 0;"); }

// ---------------------------------------------------------------------------
// GEMM (3xTF32): C[m,n] = sum_f A[m,f]*W[n,f]. 128x128 tile, BK=16, 256 thr.
// Smem tiles row-major stride 16. Logical-k remap: quad thread tig owns
// logical ks {4t,4t+1} (mma0) / {4t+2,4t+3} (mma1) at positions {t, t+4},
// identically in A and B fragments -> contraction still covers k 0..15.
// Fragment loads are single LDS.128.
// ---------------------------------------------------------------------------
__global__ __launch_bounds__(256) void gemm_qkv(
    const float* __restrict__ x,
    const float* __restrict__ Wq,
    const float* __restrict__ Wk,
    const float* __restrict__ Wv)
{
    const float* __restrict__ W = (blockIdx.z == 0) ? Wq : (blockIdx.z == 1) ? Wk : Wv;
    float* __restrict__ C       = (blockIdx.z == 0) ? g_q : (blockIdx.z == 1) ? g_k : g_v;

    __shared__ float As[2][128 * 16];
    __shared__ float Bs[2][128 * 16];

    const int tid  = threadIdx.x;
    const int m0   = blockIdx.y * 128;
    const int n0   = blockIdx.x * 128;

    const int lrow = tid >> 1;
    const int lk   = (tid & 1) * 8;

    const float* agp = x + (size_t)(m0 + lrow) * FIN + lk;
    const float* bgp = W + (size_t)(n0 + lrow) * FIN + lk;
    float* asp = &As[0][lrow * 16 + lk];
    float* bsp = &Bs[0][lrow * 16 + lk];

    const int warp  = tid >> 5;
    const int lane  = tid & 31;
    const int wm0   = (warp >> 1) * 32;
    const int wn0   = (warp & 1) * 64;
    const int gid   = lane >> 2;
    const int tig   = lane & 3;

    float acc[2][8][4];
#pragma unroll
    for (int mt = 0; mt < 2; mt++)
#pragma unroll
        for (int nt = 0; nt < 8; nt++)
#pragma unroll
            for (int i = 0; i < 4; i++) acc[mt][nt][i] = 0.f;

    const int NT = FIN / 16;

    cp_async16(asp,     agp);
    cp_async16(asp + 4, agp + 4);
    cp_async16(bsp,     bgp);
    cp_async16(bsp + 4, bgp + 4);
    cp_commit();

    for (int t = 0; t < NT; t++) {
        cp_wait0();
        __syncthreads();

        if (t + 1 < NT) {
            const int nb = (t + 1) & 1;
            const int ko = (t + 1) * 16;
            cp_async16(asp + nb * 128 * 16,     agp + ko);
            cp_async16(asp + nb * 128 * 16 + 4, agp + ko + 4);
            cp_async16(bsp + nb * 128 * 16,     bgp + ko);
            cp_async16(bsp + nb * 128 * 16 + 4, bgp + ko + 4);
            cp_commit();
        }

        const float* Ab = As[t & 1];
        const float* Bbuf = Bs[t & 1];

        float4 va[2][2];
#pragma unroll
        for (int mt = 0; mt < 2; mt++) {
            const int r0 = wm0 + mt * 16 + gid;
            va[mt][0] = *(const float4*)&Ab[(r0    ) * 16 + 4 * tig];
            va[mt][1] = *(const float4*)&Ab[(r0 + 8) * 16 + 4 * tig];
        }
        uint32_t ah0[2][4], al0[2][4], ah1[2][4], al1[2][4];
#pragma unroll
        for (int mt = 0; mt < 2; mt++) {
            split_tf32(va[mt][0].x, ah0[mt][0], al0[mt][0]);
            split_tf32(va[mt][1].x, ah0[mt][1], al0[mt][1]);
            split_tf32(va[mt][0].y, ah0[mt][2], al0[mt][2]);
            split_tf32(va[mt][1].y, ah0[mt][3], al0[mt][3]);
            split_tf32(va[mt][0].z, ah1[mt][0], al1[mt][0]);
            split_tf32(va[mt][1].z, ah1[mt][1], al1[mt][1]);
            split_tf32(va[mt][0].w, ah1[mt][2], al1[mt][2]);
            split_tf32(va[mt][1].w, ah1[mt][3], al1[mt][3]);
        }

#pragma unroll
        for (int nt = 0; nt < 8; nt++) {
            const int n = wn0 + nt * 8 + gid;
            float4 vb = *(const float4*)&Bbuf[n * 16 + 4 * tig];
            uint32_t bh0[2], bl0[2], bh1[2], bl1[2];
            split_tf32(vb.x, bh0[0], bl0[0]);
            split_tf32(vb.y, bh0[1], bl0[1]);
            split_tf32(vb.z, bh1[0], bl1[0]);
            split_tf32(vb.w, bh1[1], bl1[1]);
#pragma unroll
            for (int mt = 0; mt < 2; mt++) {
                mma_tf32(acc[mt][nt], ah0[mt], bh0);
                mma_tf32(acc[mt][nt], ah0[mt], bl0);
                mma_tf32(acc[mt][nt], al0[mt], bh0);
                mma_tf32(acc[mt][nt], ah1[mt], bh1);
                mma_tf32(acc[mt][nt], ah1[mt], bl1);
                mma_tf32(acc[mt][nt], al1[mt], bh1);
            }
        }
        __syncthreads();
    }

#pragma unroll
    for (int mt = 0; mt < 2; mt++) {
#pragma unroll
        for (int nt = 0; nt < 8; nt++) {
            const int row = m0 + wm0 + mt * 16 + gid;
            const int col = n0 + wn0 + nt * 8 + 2 * tig;
            *(float2*)&C[(size_t)row * FOUT + col] =
                make_float2(acc[mt][nt][0], acc[mt][nt][1]);
            *(float2*)&C[(size_t)(row + 8) * FOUT + col] =
                make_float2(acc[mt][nt][2], acc[mt][nt][3]);
        }
    }
}

// ---------------------------------------------------------------------------
// attn v2: block = (b, g, tile of 64 s). k/v tiles + relT in smem.
// 4 threads per s, each owns 16 d; 2 shfl_xor combine over d.
// FIX vs R4: tile loader now iterates float4-sized tasks (RROWS*16), so every
// 16-byte chunk gets its own cp.async / zero store.
// ---------------------------------------------------------------------------
#define TSs   64
#define RROWS 80          // TSs + KW - 1
#define KSTR  68

__global__ __launch_bounds__(256) void attn2(
    const float* __restrict__ rel,     // [FOUT, KW]
    float* __restrict__ out,           // [Mrows, FOUT]
    float* __restrict__ attn_out)      // [Mrows, Gg, KW]
{
    __shared__ float ks[RROWS * KSTR];
    __shared__ float vs[RROWS * KSTR];
    __shared__ float rt[KW * Dd];      // relT[j][d]

    const int b   = blockIdx.z;
    const int g   = blockIdx.y;
    const int s0  = blockIdx.x * TSs;
    const int tid = threadIdx.x;
    const int lane = tid & 31, warp = tid >> 5;
    const int sub  = lane >> 3;               // 0..3
    const int sidx = warp * 8 + (lane & 7);   // 0..63
    const int s    = s0 + sidx;
    const int m    = b * Ss + s;

    // fill k/v tiles: one float4 (16B) per task
    for (int i = tid; i < RROWS * 16; i += 256) {
        const int r = i >> 4, c = (i & 15) * 4;
        const int gr = s0 - PADK + r;
        float* kd = &ks[r * KSTR + c];
        float* vd = &vs[r * KSTR + c];
        if (gr >= 0 && gr < Ss) {
            const size_t gbase = ((size_t)(b * Ss + gr)) * FOUT + g * Dd + c;
            cp_async16(kd, &g_k[gbase]);
            cp_async16(vd, &g_v[gbase]);
        } else {
            *(float4*)kd = make_float4(0.f, 0.f, 0.f, 0.f);
            *(float4*)vd = make_float4(0.f, 0.f, 0.f, 0.f);
        }
    }
    // relT: coalesced read of the contiguous g-slice, scatter to [j][d]
    {
        const float* rsrc = rel + (size_t)g * Dd * KW;   // 1088 contiguous floats
        for (int i = tid; i < (Dd * KW) / 4; i += 256) {
            float4 v4 = *(const float4*)(rsrc + i * 4);
            float vv[4] = {v4.x, v4.y, v4.z, v4.w};
#pragma unroll
            for (int u = 0; u < 4; u++) {
                const int f = i * 4 + u;
                const int d = f / KW, j = f % KW;
                rt[j * Dd + d] = vv[u];
            }
        }
    }
    cp_commit();
    cp_wait0();
    __syncthreads();

    // q: 16 floats for this (s, sub)
    float4 q4[4];
    {
        const float* qp = &g_q[(size_t)m * FOUT + g * Dd + sub * 16];
#pragma unroll
        for (int c4 = 0; c4 < 4; c4++) q4[c4] = *(const float4*)(qp + 4 * c4);
    }

    float e[KW];
#pragma unroll
    for (int j = 0; j < KW; j++) {
        const float* kr = &ks[(sidx + j) * KSTR + sub * 16];
        const float* rr = &rt[j * Dd + sub * 16];
        float a0 = 0.f, a1 = 0.f;
#pragma unroll
        for (int c4 = 0; c4 < 4; c4++) {
            float4 kv = *(const float4*)(kr + 4 * c4);
            float4 rv = *(const float4*)(rr + 4 * c4);
            a0 = fmaf(q4[c4].x, kv.x + rv.x, a0);
            a1 = fmaf(q4[c4].y, kv.y + rv.y, a1);
            a0 = fmaf(q4[c4].z, kv.z + rv.z, a0);
            a1 = fmaf(q4[c4].w, kv.w + rv.w, a1);
        }
        float acc = a0 + a1;
        acc += __shfl_xor_sync(0xffffffffu, acc, 8);
        acc += __shfl_xor_sync(0xffffffffu, acc, 16);
        e[j] = acc;
    }

    float mx = e[0];
#pragma unroll
    for (int j = 1; j < KW; j++) mx = fmaxf(mx, e[j]);
    float sum = 0.f;
#pragma unroll
    for (int j = 0; j < KW; j++) { e[j] = __expf(e[j] - mx); sum += e[j]; }
    const float inv = 1.f / sum;
#pragma unroll
    for (int j = 0; j < KW; j++) e[j] *= inv;

    // attn output: sub t writes j in [4t, 4t+4); sub 0 also writes j=16
    {
        float* ap = &attn_out[((size_t)m * Gg + g) * KW];
#pragma unroll
        for (int u = 0; u < 4; u++) {
            const int j = sub * 4 + u;
            float val = (j == 0) ? e[0] : (j == 1) ? e[1] : (j == 2) ? e[2] :
                        (j == 3) ? e[3] : (j == 4) ? e[4] : (j == 5) ? e[5] :
                        (j == 6) ? e[6] : (j == 7) ? e[7] : (j == 8) ? e[8] :
                        (j == 9) ? e[9] : (j == 10) ? e[10] : (j == 11) ? e[11] :
                        (j == 12) ? e[12] : (j == 13) ? e[13] : (j == 14) ? e[14] : e[15];
            ap[j] = val;
        }
        if (sub == 0) ap[16] = e[16];
    }

    float4 o[4];
#pragma unroll
    for (int c4 = 0; c4 < 4; c4++) o[c4] = make_float4(0.f, 0.f, 0.f, 0.f);
#pragma unroll
    for (int j = 0; j < KW; j++) {
        const float* vr = &vs[(sidx + j) * KSTR + sub * 16];
        const float w = e[j];
#pragma unroll
        for (int c4 = 0; c4 < 4; c4++) {
            float4 vv = *(const float4*)(vr + 4 * c4);
            o[c4].x = fmaf(w, vv.x, o[c4].x);
            o[c4].y = fmaf(w, vv.y, o[c4].y);
            o[c4].z = fmaf(w, vv.z, o[c4].z);
            o[c4].w = fmaf(w, vv.w, o[c4].w);
        }
    }
    {
        float* op = &out[(size_t)m * FOUT + g * Dd + sub * 16];
#pragma unroll
        for (int c4 = 0; c4 < 4; c4++) *(float4*)(op + 4 * c4) = o[c4];
    }
}

// ---------------------------------------------------------------------------
extern "C" void kernel_launch(void* const* d_in, const int* in_sizes, int n_in,
                              void* d_out, int out_size)
{
    const float* x   = (const float*)d_in[0];
    const float* Wq  = (const float*)d_in[1];
    const float* Wk  = (const float*)d_in[2];
    const float* Wv  = (const float*)d_in[3];
    const float* rel = (const float*)d_in[4];

    float* out  = (float*)d_out;
    float* attn = out + (size_t)Mrows * FOUT;

    dim3 gg(FOUT / 128, Mrows / 128, 3);
    gemm_qkv<<<gg, 256>>>(x, Wq, Wk, Wv);

    dim3 ga(Ss / TSs, Gg, Bb);
    attn2<<<ga, 256>>>(rel, out, attn);
}

// round 6
// speedup vs baseline: 2.3590x; 1.7007x over previous
#include <cuda_runtime.h>
#include <cuda_bf16.h>
#include <cstdint>

#define Bb   4
#define Ss   4096
#define FIN  512
#define FOUT 512
#define KW   17
#define Gg   8
#define Dd   64
#define PADK 8
#define Mrows (Bb*Ss)   // 16384

__device__ float g_q[(size_t)Mrows*FOUT];
__device__ float g_k[(size_t)Mrows*FOUT];
__device__ float g_v[(size_t)Mrows*FOUT];

// bf16 hi/lo split operands (pre-pass output)
__device__ __nv_bfloat16 g_xh[(size_t)Mrows*FIN];
__device__ __nv_bfloat16 g_xl[(size_t)Mrows*FIN];
__device__ __nv_bfloat16 g_wh[3][(size_t)FOUT*FIN];
__device__ __nv_bfloat16 g_wl[3][(size_t)FOUT*FIN];

// ---------------------------------------------------------------------------
__device__ __forceinline__ void mma_bf16(float* d, const uint32_t* a,
                                         uint32_t b0, uint32_t b1) {
    asm volatile(
        "mma.sync.aligned.m16n8k16.row.col.f32.bf16.bf16.f32 "
        "{%0,%1,%2,%3}, {%4,%5,%6,%7}, {%8,%9}, {%0,%1,%2,%3};"
        : "+f"(d[0]), "+f"(d[1]), "+f"(d[2]), "+f"(d[3])
        : "r"(a[0]), "r"(a[1]), "r"(a[2]), "r"(a[3]), "r"(b0), "r"(b1));
}

__device__ __forceinline__ void cp_async16(void* smem, const void* gmem) {
    uint32_t s = (uint32_t)__cvta_generic_to_shared(smem);
    asm volatile("cp.async.cg.shared.global [%0], [%1], 16;" :: "r"(s), "l"(gmem));
}
__device__ __forceinline__ void cp_commit() { asm volatile("cp.async.commit_group;"); }
__device__ __forceinline__ void cp_wait0() { asm volatile("cp.async.wait_group 0;"); }

__device__ __forceinline__ uint64_t pack4bf(__nv_bfloat16 a, __nv_bfloat16 b,
                                            __nv_bfloat16 c, __nv_bfloat16 d) {
    return (uint64_t)__bfloat16_as_ushort(a)
         | ((uint64_t)__bfloat16_as_ushort(b) << 16)
         | ((uint64_t)__bfloat16_as_ushort(c) << 32)
         | ((uint64_t)__bfloat16_as_ushort(d) << 48);
}

// ---------------------------------------------------------------------------
// Pre-pass: split fp32 -> bf16 hi + bf16 lo (residual). One float4 per thread.
// ---------------------------------------------------------------------------
__global__ __launch_bounds__(256) void split_x(const float* __restrict__ src) {
    const size_t i = (size_t)blockIdx.x * 256 + threadIdx.x;
    float4 v = ((const float4*)src)[i];
    float a[4] = {v.x, v.y, v.z, v.w};
    __nv_bfloat16 h[4], l[4];
#pragma unroll
    for (int u = 0; u < 4; u++) {
        h[u] = __float2bfloat16(a[u]);
        l[u] = __float2bfloat16(a[u] - __bfloat162float(h[u]));
    }
    ((uint64_t*)g_xh)[i] = pack4bf(h[0], h[1], h[2], h[3]);
    ((uint64_t*)g_xl)[i] = pack4bf(l[0], l[1], l[2], l[3]);
}

__global__ __launch_bounds__(256) void split_w(const float* __restrict__ Wq,
                                               const float* __restrict__ Wk,
                                               const float* __restrict__ Wv) {
    const int z = blockIdx.z;
    const float* src = (z == 0) ? Wq : (z == 1) ? Wk : Wv;
    const size_t i = (size_t)blockIdx.x * 256 + threadIdx.x;
    float4 v = ((const float4*)src)[i];
    float a[4] = {v.x, v.y, v.z, v.w};
    __nv_bfloat16 h[4], l[4];
#pragma unroll
    for (int u = 0; u < 4; u++) {
        h[u] = __float2bfloat16(a[u]);
        l[u] = __float2bfloat16(a[u] - __bfloat162float(h[u]));
    }
    ((uint64_t*)g_wh[z])[i] = pack4bf(h[0], h[1], h[2], h[3]);
    ((uint64_t*)g_wl[z])[i] = pack4bf(l[0], l[1], l[2], l[3]);
}

// ---------------------------------------------------------------------------
// GEMM (3xBF16): C[m,n] = sum_f A[m,f]*W[n,f] with A,W pre-split hi/lo bf16.
// 128x128 tile, BK=16, 256 thr, warp tile 32x64. acc += ah*bh + ah*bl + al*bh.
// k-slot permutation: logical ks {4t..4t+3} occupy mma slots {2t,2t+1,2t+8,2t+9}
// for both A and B -> every fragment is one aligned LDS.64.
// ---------------------------------------------------------------------------
__global__ __launch_bounds__(256) void gemm_qkv(void) {
    const int z = blockIdx.z;
    const __nv_bfloat16* __restrict__ Wh = g_wh[z];
    const __nv_bfloat16* __restrict__ Wl = g_wl[z];
    float* __restrict__ C = (z == 0) ? g_q : (z == 1) ? g_k : g_v;

    __shared__ __nv_bfloat16 Ah[2][128 * 16];
    __shared__ __nv_bfloat16 Al[2][128 * 16];
    __shared__ __nv_bfloat16 Bh[2][128 * 16];
    __shared__ __nv_bfloat16 Bl[2][128 * 16];

    const int tid  = threadIdx.x;
    const int m0   = blockIdx.y * 128;
    const int n0   = blockIdx.x * 128;

    const int lrow = tid >> 1;
    const int lk   = (tid & 1) * 8;

    const __nv_bfloat16* agh = g_xh + (size_t)(m0 + lrow) * FIN + lk;
    const __nv_bfloat16* agl = g_xl + (size_t)(m0 + lrow) * FIN + lk;
    const __nv_bfloat16* bgh = Wh   + (size_t)(n0 + lrow) * FIN + lk;
    const __nv_bfloat16* bgl = Wl   + (size_t)(n0 + lrow) * FIN + lk;
    __nv_bfloat16* sah = &Ah[0][lrow * 16 + lk];
    __nv_bfloat16* sal = &Al[0][lrow * 16 + lk];
    __nv_bfloat16* sbh = &Bh[0][lrow * 16 + lk];
    __nv_bfloat16* sbl = &Bl[0][lrow * 16 + lk];

    const int warp = tid >> 5;
    const int lane = tid & 31;
    const int wm0  = (warp >> 1) * 32;
    const int wn0  = (warp & 1) * 64;
    const int gid  = lane >> 2;
    const int tig  = lane & 3;

    float acc[2][8][4];
#pragma unroll
    for (int mt = 0; mt < 2; mt++)
#pragma unroll
        for (int nt = 0; nt < 8; nt++)
#pragma unroll
            for (int i = 0; i < 4; i++) acc[mt][nt][i] = 0.f;

    const int NT = FIN / 16;

    cp_async16(sah, agh);
    cp_async16(sal, agl);
    cp_async16(sbh, bgh);
    cp_async16(sbl, bgl);
    cp_commit();

    for (int t = 0; t < NT; t++) {
        cp_wait0();
        __syncthreads();

        if (t + 1 < NT) {
            const int nb = (t + 1) & 1;
            const int ko = (t + 1) * 16;
            cp_async16(sah + nb * 128 * 16, agh + ko);
            cp_async16(sal + nb * 128 * 16, agl + ko);
            cp_async16(sbh + nb * 128 * 16, bgh + ko);
            cp_async16(sbl + nb * 128 * 16, bgl + ko);
            cp_commit();
        }

        const __nv_bfloat16* Abh = Ah[t & 1];
        const __nv_bfloat16* Abl = Al[t & 1];
        const __nv_bfloat16* Bbh = Bh[t & 1];
        const __nv_bfloat16* Bbl = Bl[t & 1];

        uint32_t a_h[2][4], a_l[2][4];
#pragma unroll
        for (int mt = 0; mt < 2; mt++) {
            const int r0 = wm0 + mt * 16 + gid;
            uint2 v0 = *(const uint2*)&Abh[(r0    ) * 16 + 4 * tig];
            uint2 v1 = *(const uint2*)&Abh[(r0 + 8) * 16 + 4 * tig];
            a_h[mt][0] = v0.x; a_h[mt][1] = v1.x; a_h[mt][2] = v0.y; a_h[mt][3] = v1.y;
            uint2 w0 = *(const uint2*)&Abl[(r0    ) * 16 + 4 * tig];
            uint2 w1 = *(const uint2*)&Abl[(r0 + 8) * 16 + 4 * tig];
            a_l[mt][0] = w0.x; a_l[mt][1] = w1.x; a_l[mt][2] = w0.y; a_l[mt][3] = w1.y;
        }

#pragma unroll
        for (int nt = 0; nt < 8; nt++) {
            const int n = wn0 + nt * 8 + gid;
            uint2 vbh = *(const uint2*)&Bbh[n * 16 + 4 * tig];
            uint2 vbl = *(const uint2*)&Bbl[n * 16 + 4 * tig];
#pragma unroll
            for (int mt = 0; mt < 2; mt++) {
                mma_bf16(acc[mt][nt], a_h[mt], vbh.x, vbh.y);  // hi*hi
                mma_bf16(acc[mt][nt], a_h[mt], vbl.x, vbl.y);  // hi*lo
                mma_bf16(acc[mt][nt], a_l[mt], vbh.x, vbh.y);  // lo*hi
            }
        }
        __syncthreads();
    }

#pragma unroll
    for (int mt = 0; mt < 2; mt++) {
#pragma unroll
        for (int nt = 0; nt < 8; nt++) {
            const int row = m0 + wm0 + mt * 16 + gid;
            const int col = n0 + wn0 + nt * 8 + 2 * tig;
            *(float2*)&C[(size_t)row * FOUT + col] =
                make_float2(acc[mt][nt][0], acc[mt][nt][1]);
            *(float2*)&C[(size_t)(row + 8) * FOUT + col] =
                make_float2(acc[mt][nt][2], acc[mt][nt][3]);
        }
    }
}

// ---------------------------------------------------------------------------
// attn v2 (unchanged from R5): block = (b, g, 64 s). k/v tiles + relT in smem.
// ---------------------------------------------------------------------------
#define TSs   64
#define RROWS 80          // TSs + KW - 1
#define KSTR  68

__global__ __launch_bounds__(256) void attn2(
    const float* __restrict__ rel,     // [FOUT, KW]
    float* __restrict__ out,           // [Mrows, FOUT]
    float* __restrict__ attn_out)      // [Mrows, Gg, KW]
{
    __shared__ float ks[RROWS * KSTR];
    __shared__ float vs[RROWS * KSTR];
    __shared__ float rt[KW * Dd];      // relT[j][d]

    const int b   = blockIdx.z;
    const int g   = blockIdx.y;
    const int s0  = blockIdx.x * TSs;
    const int tid = threadIdx.x;
    const int lane = tid & 31, warp = tid >> 5;
    const int sub  = lane >> 3;               // 0..3
    const int sidx = warp * 8 + (lane & 7);   // 0..63
    const int s    = s0 + sidx;
    const int m    = b * Ss + s;

    for (int i = tid; i < RROWS * 16; i += 256) {
        const int r = i >> 4, c = (i & 15) * 4;
        const int gr = s0 - PADK + r;
        float* kd = &ks[r * KSTR + c];
        float* vd = &vs[r * KSTR + c];
        if (gr >= 0 && gr < Ss) {
            const size_t gbase = ((size_t)(b * Ss + gr)) * FOUT + g * Dd + c;
            cp_async16(kd, &g_k[gbase]);
            cp_async16(vd, &g_v[gbase]);
        } else {
            *(float4*)kd = make_float4(0.f, 0.f, 0.f, 0.f);
            *(float4*)vd = make_float4(0.f, 0.f, 0.f, 0.f);
        }
    }
    {
        const float* rsrc = rel + (size_t)g * Dd * KW;
        for (int i = tid; i < (Dd * KW) / 4; i += 256) {
            float4 v4 = *(const float4*)(rsrc + i * 4);
            float vv[4] = {v4.x, v4.y, v4.z, v4.w};
#pragma unroll
            for (int u = 0; u < 4; u++) {
                const int f = i * 4 + u;
                const int d = f / KW, j = f % KW;
                rt[j * Dd + d] = vv[u];
            }
        }
    }
    cp_commit();
    cp_wait0();
    __syncthreads();

    float4 q4[4];
    {
        const float* qp = &g_q[(size_t)m * FOUT + g * Dd + sub * 16];
#pragma unroll
        for (int c4 = 0; c4 < 4; c4++) q4[c4] = *(const float4*)(qp + 4 * c4);
    }

    float e[KW];
#pragma unroll
    for (int j = 0; j < KW; j++) {
        const float* kr = &ks[(sidx + j) * KSTR + sub * 16];
        const float* rr = &rt[j * Dd + sub * 16];
        float a0 = 0.f, a1 = 0.f;
#pragma unroll
        for (int c4 = 0; c4 < 4; c4++) {
            float4 kv = *(const float4*)(kr + 4 * c4);
            float4 rv = *(const float4*)(rr + 4 * c4);
            a0 = fmaf(q4[c4].x, kv.x + rv.x, a0);
            a1 = fmaf(q4[c4].y, kv.y + rv.y, a1);
            a0 = fmaf(q4[c4].z, kv.z + rv.z, a0);
            a1 = fmaf(q4[c4].w, kv.w + rv.w, a1);
        }
        float acc = a0 + a1;
        acc += __shfl_xor_sync(0xffffffffu, acc, 8);
        acc += __shfl_xor_sync(0xffffffffu, acc, 16);
        e[j] = acc;
    }

    float mx = e[0];
#pragma unroll
    for (int j = 1; j < KW; j++) mx = fmaxf(mx, e[j]);
    float sum = 0.f;
#pragma unroll
    for (int j = 0; j < KW; j++) { e[j] = __expf(e[j] - mx); sum += e[j]; }
    const float inv = 1.f / sum;
#pragma unroll
    for (int j = 0; j < KW; j++) e[j] *= inv;

    {
        float* ap = &attn_out[((size_t)m * Gg + g) * KW];
#pragma unroll
        for (int u = 0; u < 4; u++) {
            const int j = sub * 4 + u;
            float val = (j == 0) ? e[0] : (j == 1) ? e[1] : (j == 2) ? e[2] :
                        (j == 3) ? e[3] : (j == 4) ? e[4] : (j == 5) ? e[5] :
                        (j == 6) ? e[6] : (j == 7) ? e[7] : (j == 8) ? e[8] :
                        (j == 9) ? e[9] : (j == 10) ? e[10] : (j == 11) ? e[11] :
                        (j == 12) ? e[12] : (j == 13) ? e[13] : (j == 14) ? e[14] : e[15];
            ap[j] = val;
        }
        if (sub == 0) ap[16] = e[16];
    }

    float4 o[4];
#pragma unroll
    for (int c4 = 0; c4 < 4; c4++) o[c4] = make_float4(0.f, 0.f, 0.f, 0.f);
#pragma unroll
    for (int j = 0; j < KW; j++) {
        const float* vr = &vs[(sidx + j) * KSTR + sub * 16];
        const float w = e[j];
#pragma unroll
        for (int c4 = 0; c4 < 4; c4++) {
            float4 vv = *(const float4*)(vr + 4 * c4);
            o[c4].x = fmaf(w, vv.x, o[c4].x);
            o[c4].y = fmaf(w, vv.y, o[c4].y);
            o[c4].z = fmaf(w, vv.z, o[c4].z);
            o[c4].w = fmaf(w, vv.w, o[c4].w);
        }
    }
    {
        float* op = &out[(size_t)m * FOUT + g * Dd + sub * 16];
#pragma unroll
        for (int c4 = 0; c4 < 4; c4++) *(float4*)(op + 4 * c4) = o[c4];
    }
}

// ---------------------------------------------------------------------------
extern "C" void kernel_launch(void* const* d_in, const int* in_sizes, int n_in,
                              void* d_out, int out_size)
{
    const float* x   = (const float*)d_in[0];
    const float* Wq  = (const float*)d_in[1];
    const float* Wk  = (const float*)d_in[2];
    const float* Wv  = (const float*)d_in[3];
    const float* rel = (const float*)d_in[4];

    float* out  = (float*)d_out;
    float* attn = out + (size_t)Mrows * FOUT;

    split_x<<<(Mrows * FIN / 4) / 256, 256>>>(x);
    split_w<<<dim3((FOUT * FIN / 4) / 256, 1, 3), 256>>>(Wq, Wk, Wv);

    dim3 gg(FOUT / 128, Mrows / 128, 3);
    gemm_qkv<<<gg, 256>>>();

    dim3 ga(Ss / TSs, Gg, Bb);
    attn2<<<ga, 256>>>(rel, out, attn);
}